// round 16
// baseline (speedup 1.0000x reference)
#include <cuda_runtime.h>
#include <cuda_bf16.h>
#include <stdint.h>

#define NTOK   16384
#define DIM    256
#define NCODES 8192

// Device-global scratch (device-code references ONLY — GB300 ATS trap:
// passing __device__ symbols as host-side kernel args reads host memory).
__device__ unsigned long long g_key[NTOK];
__device__ float  g_rown[NTOK];
__device__ float  g_coden[NCODES];
__device__ double g_partial[1024];
__device__ float  g_xTd[DIM * 2 * NTOK];   // x transposed + duplicated: [d][2*tok]
__device__ float  g_cT[DIM * NCODES];      // cb transposed: [d][code]

// ---------------------------------------------------------------------------
__device__ __forceinline__ uint32_t smem_u32(const void* p) {
    uint32_t a;
    asm("{ .reg .u64 t; cvta.to.shared.u64 t, %1; cvt.u32.u64 %0, t; }" : "=r"(a) : "l"(p));
    return a;
}
__device__ __forceinline__ void unpackf2(unsigned long long v, float& lo, float& hi) {
    asm("mov.b64 {%0, %1}, %2;" : "=f"(lo), "=f"(hi) : "l"(v));
}
// Packed dual fp32 FMA: c.lo += a.lo*b.lo; c.hi += a.hi*b.hi (each IEEE fp32).
__device__ __forceinline__ void fma2(unsigned long long& c, unsigned long long a,
                                     unsigned long long b) {
    asm("fma.rn.f32x2 %0, %1, %2, %0;" : "+l"(c) : "l"(a), "l"(b));
}
#define CPA(dst, src) \
    asm volatile("cp.async.cg.shared.global [%0], [%1], 16;" :: "r"(dst), "l"(src))
#define CPA_COMMIT() asm volatile("cp.async.commit_group;" ::: "memory")
#define CPA_WAIT0()  asm volatile("cp.async.wait_group 0;" ::: "memory")

// ---------------------------------------------------------------------------
// 32x32 tiled transpose. mode 0: x -> g_xTd (duplicated pairs). mode 1: cb -> g_cT.
__global__ void k_tr(const float* __restrict__ src, int mode) {
    __shared__ float t[32][33];
    const int tx = threadIdx.x & 31, ty = threadIdx.x >> 5;   // 256 thr
    const int bx = blockIdx.x * 32;   // token/code base
    const int by = blockIdx.y * 32;   // d base
#pragma unroll
    for (int i = ty; i < 32; i += 8)
        t[i][tx] = src[(size_t)(bx + i) * DIM + by + tx];
    __syncthreads();
    if (mode == 0) {
        float2* dst = reinterpret_cast<float2*>(g_xTd);
#pragma unroll
        for (int i = ty; i < 32; i += 8) {
            float v = t[tx][i];
            dst[(size_t)(by + i) * NTOK + bx + tx] = make_float2(v, v);
        }
    } else {
#pragma unroll
        for (int i = ty; i < 32; i += 8)
            g_cT[(size_t)(by + i) * NCODES + bx + tx] = t[tx][i];
    }
}

__global__ void k_init(void) {
    int n = blockIdx.x * 256 + threadIdx.x;
    if (n < NTOK) g_key[n] = ~0ull;
}

__global__ void k_norm(const float* __restrict__ src, int nrows, int which) {
    int gwarp = (blockIdx.x * blockDim.x + threadIdx.x) >> 5;
    int lane  = threadIdx.x & 31;
    if (gwarp >= nrows) return;
    const float4* s4 = reinterpret_cast<const float4*>(src) + (size_t)gwarp * 64;
    float a = 0.0f;
#pragma unroll
    for (int it = 0; it < 2; it++) {
        float4 v = s4[it * 32 + lane];
        a = __fadd_rn(a, __fmul_rn(v.x, v.x));
        a = __fadd_rn(a, __fmul_rn(v.y, v.y));
        a = __fadd_rn(a, __fmul_rn(v.z, v.z));
        a = __fadd_rn(a, __fmul_rn(v.w, v.w));
    }
#pragma unroll
    for (int off = 16; off >= 1; off >>= 1)
        a += __shfl_xor_sync(0xffffffffu, a, off);
    if (lane == 0) { if (which == 0) g_rown[gwarp] = a; else g_coden[gwarp] = a; }
}

// ---------------------------------------------------------------------------
// Fused exact-fp32 GEMM + argmin, FFMA2 + LDS.128, spill-free (32 u64 accums).
// CTA = 128 rows x 128 codes. Thread (tx 0..15, ty 0..15):
//   rows  8*ty .. 8*ty+7          (x pre-duplicated: LDS.128 -> 2 bcast pairs)
//   codes 4*tx..4*tx+3, 64+4*tx..64+4*tx+3   (2 LDS.128 -> 4 natural pairs)
// Each output dot = one ascending-d fp32 FMA chain in one f32x2 lane
// (bit-identical to scalar FFMA). dist = fsub(fadd(r,c), 2t);
// key = (dist_bits<<32)|k reproduces jnp.argmin's first-index tie-break.
__global__ void __launch_bounds__(256) k_main() {
    extern __shared__ float sm[];    // xs: 2 x 8192 f (dup) | es: 2 x 4096 f  = 96KB
    const int tid = threadIdx.x;
    const int tx  = tid & 15;
    const int ty  = tid >> 4;
    const int rowbase = blockIdx.x * 128;
    const int kbase   = blockIdx.y * 128;
    const uint32_t smb = smem_u32(sm);

    unsigned long long acc[8][4];
#pragma unroll
    for (int r = 0; r < 8; r++)
#pragma unroll
        for (int q = 0; q < 4; q++) acc[r][q] = 0ull;

#define FILLX(ct, b)                                                             \
    do {                                                                         \
        _Pragma("unroll")                                                        \
        for (int it = 0; it < 8; it++) {                                         \
            int f = it * 256 + tid;          /* 2048 float4 */                   \
            int dlx = f >> 6, g = f & 63;                                        \
            CPA(smb + ((b) * 8192 + dlx * 256 + g * 4) * 4,                      \
                &g_xTd[(size_t)((ct) * 32 + dlx) * (2 * NTOK) + 2 * rowbase + g * 4]); \
        }                                                                        \
    } while (0)
#define FILLE(ct, b)                                                             \
    do {                                                                         \
        _Pragma("unroll")                                                        \
        for (int it = 0; it < 4; it++) {                                         \
            int f = it * 256 + tid;          /* 1024 float4 */                   \
            int dle = f >> 5, g = f & 31;                                        \
            CPA(smb + (16384 + (b) * 4096 + dle * 128 + g * 4) * 4,              \
                &g_cT[(size_t)((ct) * 32 + dle) * NCODES + kbase + g * 4]);      \
        }                                                                        \
    } while (0)

    FILLX(0, 0); FILLE(0, 0);
    CPA_COMMIT();
    CPA_WAIT0();
    __syncthreads();

#pragma unroll 1
    for (int ct = 0; ct < 8; ct++) {
        if (ct < 7) { FILLX(ct + 1, (ct + 1) & 1); FILLE(ct + 1, (ct + 1) & 1); CPA_COMMIT(); }
        const float* xs = sm + (ct & 1) * 8192;
        const float* es = sm + 16384 + (ct & 1) * 4096;
#pragma unroll 2
        for (int d = 0; d < 32; d++) {
            ulonglong2 xa[4], eb[2];
#pragma unroll
            for (int i = 0; i < 4; i++)
                xa[i] = *reinterpret_cast<const ulonglong2*>(
                            &xs[d * 256 + (4 * ty + i) * 4]);
            eb[0] = *reinterpret_cast<const ulonglong2*>(&es[d * 128 + 4 * tx]);
            eb[1] = *reinterpret_cast<const ulonglong2*>(&es[d * 128 + 64 + 4 * tx]);
#pragma unroll
            for (int i = 0; i < 4; i++) {
                fma2(acc[2 * i][0],     xa[i].x, eb[0].x);
                fma2(acc[2 * i][1],     xa[i].x, eb[0].y);
                fma2(acc[2 * i][2],     xa[i].x, eb[1].x);
                fma2(acc[2 * i][3],     xa[i].x, eb[1].y);
                fma2(acc[2 * i + 1][0], xa[i].y, eb[0].x);
                fma2(acc[2 * i + 1][1], xa[i].y, eb[0].y);
                fma2(acc[2 * i + 1][2], xa[i].y, eb[1].x);
                fma2(acc[2 * i + 1][3], xa[i].y, eb[1].y);
            }
        }
        if (ct < 7) { CPA_WAIT0(); __syncthreads(); }
    }

    // Epilogue: distances + lexicographic argmin.
    unsigned long long bk[8];
#pragma unroll
    for (int r = 0; r < 8; r++) bk[r] = ~0ull;
#pragma unroll
    for (int r = 0; r < 8; r++) {
        float rr = g_rown[rowbase + 8 * ty + r];
#pragma unroll
        for (int q = 0; q < 4; q++) {
            int k0 = kbase + (q >> 1) * 64 + 4 * tx + (q & 1) * 2;
            float cn0 = g_coden[k0], cn1 = g_coden[k0 + 1];
            float tlo, thi;
            unpackf2(acc[r][q], tlo, thi);
            float d0 = __fsub_rn(__fadd_rn(rr, cn0), 2.0f * tlo);
            float d1 = __fsub_rn(__fadd_rn(rr, cn1), 2.0f * thi);
            unsigned long long w;
            w = ((unsigned long long)__float_as_uint(d0) << 32) | (unsigned)k0;
            if (w < bk[r]) bk[r] = w;
            w = ((unsigned long long)__float_as_uint(d1) << 32) | (unsigned)(k0 + 1);
            if (w < bk[r]) bk[r] = w;
        }
    }
    // reduce across the 16 tx lanes sharing this ty (xor 8..1 stays in half-warp)
#pragma unroll
    for (int r = 0; r < 8; r++) {
        unsigned long long k = bk[r];
#pragma unroll
        for (int off = 8; off >= 1; off >>= 1) {
            unsigned long long o = __shfl_xor_sync(0xffffffffu, k, off);
            if (o < k) k = o;
        }
        if (tx == 0) atomicMin(&g_key[rowbase + 8 * ty + r], k);
    }
}

// ---------------------------------------------------------------------------
__global__ void k_gather(const float* __restrict__ x, const float* __restrict__ cb,
                         float* __restrict__ out, int out_size) {
    double ls = 0.0;
    const int total = NTOK * DIM;
    for (int e = blockIdx.x * 256 + threadIdx.x; e < total; e += 1024 * 256) {
        int n = e >> 8, d = e & 255;
        int idx = (int)(unsigned)(g_key[n] & 0xffffffffull);
        float q  = __ldg(&cb[idx * DIM + d]);
        float xv = x[e];
        float diff = __fsub_rn(q, xv);
        if (e < out_size) out[e] = __fadd_rn(xv, diff);
        ls += (double)__fmul_rn(diff, diff);
    }
#pragma unroll
    for (int off = 16; off >= 1; off >>= 1)
        ls += __shfl_xor_sync(0xffffffffu, ls, off);
    __shared__ double ws[8];
    if ((threadIdx.x & 31) == 0) ws[threadIdx.x >> 5] = ls;
    __syncthreads();
    if (threadIdx.x == 0) {
        double t = 0.0;
        for (int w = 0; w < 8; w++) t += ws[w];
        g_partial[blockIdx.x] = t;
    }
}

__global__ void k_finalize(float* __restrict__ out, int out_size) {
    if (blockIdx.x < 64) {
        int n = blockIdx.x * 256 + threadIdx.x;
        int pos = NTOK * DIM + n;
        if (pos < out_size)
            out[pos] = (float)(unsigned)(g_key[n] & 0xffffffffull);
    } else if (threadIdx.x == 0) {
        double s = 0.0;
        for (int b = 0; b < 1024; b++) s += g_partial[b];
        int pos = NTOK * DIM + NTOK;
        if (pos < out_size)
            out[pos] = 0.25f * (float)(s / (double)(NTOK * DIM));
    }
}

// ---------------------------------------------------------------------------
extern "C" void kernel_launch(void* const* d_in, const int* in_sizes, int n_in,
                              void* d_out, int out_size) {
    const float* x  = (const float*)d_in[0];
    const float* cb = (const float*)d_in[1];
    if (n_in >= 2 && in_sizes[0] == NCODES * DIM) {
        cb = (const float*)d_in[0];
        x  = (const float*)d_in[1];
    }
    float* out = (float*)d_out;

    const int smem = 96 * 1024;
    cudaFuncSetAttribute(k_main, cudaFuncAttributeMaxDynamicSharedMemorySize, smem);

    k_tr<<<dim3(NTOK / 32, DIM / 32), 256>>>(x, 0);
    k_tr<<<dim3(NCODES / 32, DIM / 32), 256>>>(cb, 1);
    k_init<<<(NTOK + 255) / 256, 256>>>();
    k_norm<<<NTOK / 8, 256>>>(x, NTOK, 0);
    k_norm<<<NCODES / 8, 256>>>(cb, NCODES, 1);
    k_main<<<dim3(NTOK / 128, NCODES / 128), 256, smem>>>();
    k_gather<<<1024, 256>>>(x, cb, out, out_size);
    k_finalize<<<65, 256>>>(out, out_size);
}